// round 1
// baseline (speedup 1.0000x reference)
#include <cuda_runtime.h>

#define T_STEPS 800
#define B_DIM   128
#define S_DIM   500
#define M_DIM   (T_STEPS * B_DIM)   /* 102400 */
#define BS      (B_DIM * S_DIM)     /* 64000  */

// Scratch: total[t,b,s] = input - err @ W^T   (204.8 MB, static device global)
__device__ float g_total[(size_t)M_DIM * S_DIM];

// ---------------------------------------------------------------------------
// Kernel 1: C[M,N] = input[M,N] - err[M,K] * W[N,K]^T   (M=102400, N=K=500)
// 128x128 block tile, BK=16, 256 threads, 8x8 per-thread micro-tile,
// double-buffered shared memory.
// ---------------------------------------------------------------------------
__global__ __launch_bounds__(256, 2) void fused_gemm_kernel(
    const float* __restrict__ input,
    const float* __restrict__ err,
    const float* __restrict__ W)
{
    const int K = S_DIM;
    const int N = S_DIM;
    const int BK = 16;
    const int KT = (K + BK - 1) / BK;   // 32 k-tiles (last one has 4 valid cols)

    __shared__ float As[2][BK][128];
    __shared__ float Bs[2][BK][128];

    const int tid = threadIdx.x;
    const int m0  = blockIdx.y * 128;
    const int n0  = blockIdx.x * 128;

    // global-load mapping: each thread loads 2 float4 of A and 2 float4 of B
    const int lrow = tid >> 2;          // 0..63
    const int lcol = (tid & 3) << 2;    // 0,4,8,12

    const float* aptr0 = err + (size_t)(m0 + lrow) * K + lcol;
    const float* aptr1 = aptr0 + (size_t)64 * K;
    const int nr0 = n0 + lrow;
    const int nr1 = n0 + lrow + 64;
    const float* bptr0 = W + (size_t)nr0 * K + lcol;
    const float* bptr1 = W + (size_t)nr1 * K + lcol;

    float4 pa0, pa1, pb0, pb1;
    const float4 f4z = make_float4(0.f, 0.f, 0.f, 0.f);

    auto LOADG = [&](int kt) {
        const int k0 = kt * BK;
        const bool kok = (k0 + lcol + 4 <= K);
        pa0 = kok ? *(const float4*)(aptr0 + k0) : f4z;
        pa1 = kok ? *(const float4*)(aptr1 + k0) : f4z;
        pb0 = (kok && nr0 < N) ? *(const float4*)(bptr0 + k0) : f4z;
        pb1 = (kok && nr1 < N) ? *(const float4*)(bptr1 + k0) : f4z;
    };
    auto STOS = [&](int buf) {
        As[buf][lcol + 0][lrow]      = pa0.x;
        As[buf][lcol + 1][lrow]      = pa0.y;
        As[buf][lcol + 2][lrow]      = pa0.z;
        As[buf][lcol + 3][lrow]      = pa0.w;
        As[buf][lcol + 0][lrow + 64] = pa1.x;
        As[buf][lcol + 1][lrow + 64] = pa1.y;
        As[buf][lcol + 2][lrow + 64] = pa1.z;
        As[buf][lcol + 3][lrow + 64] = pa1.w;
        Bs[buf][lcol + 0][lrow]      = pb0.x;
        Bs[buf][lcol + 1][lrow]      = pb0.y;
        Bs[buf][lcol + 2][lrow]      = pb0.z;
        Bs[buf][lcol + 3][lrow]      = pb0.w;
        Bs[buf][lcol + 0][lrow + 64] = pb1.x;
        Bs[buf][lcol + 1][lrow + 64] = pb1.y;
        Bs[buf][lcol + 2][lrow + 64] = pb1.z;
        Bs[buf][lcol + 3][lrow + 64] = pb1.w;
    };

    const int tx = tid & 15;   // n-dir, 8 cols each
    const int ty = tid >> 4;   // m-dir, 8 rows each

    float acc[8][8];
#pragma unroll
    for (int i = 0; i < 8; ++i)
#pragma unroll
        for (int j = 0; j < 8; ++j) acc[i][j] = 0.f;

    LOADG(0);
    STOS(0);
    __syncthreads();

    for (int kt = 0; kt < KT; ++kt) {
        const int buf = kt & 1;
        if (kt + 1 < KT) LOADG(kt + 1);

#pragma unroll
        for (int kk = 0; kk < BK; ++kk) {
            float4 a0 = *(const float4*)&As[buf][kk][ty * 8];
            float4 a1 = *(const float4*)&As[buf][kk][ty * 8 + 4];
            float4 b0 = *(const float4*)&Bs[buf][kk][tx * 8];
            float4 b1 = *(const float4*)&Bs[buf][kk][tx * 8 + 4];
            float a[8] = {a0.x, a0.y, a0.z, a0.w, a1.x, a1.y, a1.z, a1.w};
            float b[8] = {b0.x, b0.y, b0.z, b0.w, b1.x, b1.y, b1.z, b1.w};
#pragma unroll
            for (int i = 0; i < 8; ++i)
#pragma unroll
                for (int j = 0; j < 8; ++j)
                    acc[i][j] += a[i] * b[j];
        }

        if (kt + 1 < KT) STOS(buf ^ 1);
        __syncthreads();
    }

    // Epilogue: g_total = input - acc   (n granularity is multiples of 4; N=500)
#pragma unroll
    for (int i = 0; i < 8; ++i) {
        const int m = m0 + ty * 8 + i;
        const float* inrow = input + (size_t)m * N;
        float* orow = g_total + (size_t)m * N;
#pragma unroll
        for (int jv = 0; jv < 2; ++jv) {
            const int n = n0 + tx * 8 + jv * 4;
            if (n + 4 <= N) {
                float4 iv = *(const float4*)(inrow + n);
                float4 ov;
                ov.x = iv.x - acc[i][jv * 4 + 0];
                ov.y = iv.y - acc[i][jv * 4 + 1];
                ov.z = iv.z - acc[i][jv * 4 + 2];
                ov.w = iv.w - acc[i][jv * 4 + 3];
                *(float4*)(orow + n) = ov;
            } else {
#pragma unroll
                for (int jj = 0; jj < 4; ++jj)
                    if (n + jj < N)
                        orow[n + jj] = inrow[n + jj] - acc[i][jv * 4 + jj];
            }
        }
    }
}

// ---------------------------------------------------------------------------
// Kernel 2: per-lane 800-step recurrence. One thread per (b,s) lane.
//   reset = H(mem - thr); syn = a*syn + tot; mem = (b*mem + syn)*(1-reset);
//   spk = H(mem - thr);   trace = k*trace + spk
// ---------------------------------------------------------------------------
__global__ __launch_bounds__(256) void scan_kernel(
    float* __restrict__ spks, float* __restrict__ traces)
{
    const int i = blockIdx.x * 256 + threadIdx.x;
    if (i >= BS) return;

    const float ALPHA  = (float)(1.0 - 0.25 / 10.0);
    const float BETA   = (float)(1.0 - 0.25 / 20.0);
    const float KAPPA  = (float)(1.0 - 0.25 / 30.0);
    const float THRESH = 0.4f;

    float syn = 0.f, mem = 0.f, tr = 0.f;
    const float* p  = g_total + i;
    float* ps = spks + i;
    float* pt = traces + i;

#pragma unroll 4
    for (int t = 0; t < T_STEPS; ++t) {
        const float tot = __ldg(p + (size_t)t * BS);
        const float reset = (mem - THRESH) > 0.f ? 1.f : 0.f;
        syn = ALPHA * syn + tot;
        mem = (BETA * mem + syn) * (1.f - reset);
        const float spk = (mem - THRESH) > 0.f ? 1.f : 0.f;
        tr = KAPPA * tr + spk;
        ps[(size_t)t * BS] = spk;
        pt[(size_t)t * BS] = tr;
    }
}

// ---------------------------------------------------------------------------
extern "C" void kernel_launch(void* const* d_in, const int* in_sizes, int n_in,
                              void* d_out, int out_size)
{
    const float* input = (const float*)d_in[0];   // (T,B,S)
    const float* err   = (const float*)d_in[1];   // (T,B,S)
    const float* W     = (const float*)d_in[2];   // (S,S)
    float* out = (float*)d_out;                   // [spks | traces]

    dim3 grid((S_DIM + 127) / 128, M_DIM / 128);  // (4, 800)
    fused_gemm_kernel<<<grid, 256>>>(input, err, W);

    scan_kernel<<<(BS + 255) / 256, 256>>>(out, out + (size_t)T_STEPS * BS);
}